// round 2
// baseline (speedup 1.0000x reference)
#include <cuda_runtime.h>

// MixEHR_Seed: B=64, V=10000, K=64
// Inputs (metadata order): batch_BOW [B,V], seeds [V,K], exp_m [B,K],
//                          exp_s [V,K], exp_n [V,K], pi [K]
// Output (concatenated fp32): temp_exp_m_batch [B,K]=4096, temp_exp_n [V,K]=640000,
//                             temp_exp_s [V,K]=640000, gamma_sr_sum [K]=64, exp_q_z [1]

#define KD    64
#define BD    64
#define VD    10000
#define ETA_F  0.1f
#define BETA_F 0.05f
#define MU_F   0.05f
#define MINI_F 1e-6f

#define OFF_N   4096
#define OFF_S   644096
#define OFF_GSR 1284096
#define OFF_QZ  1284160

__device__ float g_colS[KD];
__device__ float g_colES[KD];
__device__ float g_colEN[KD];
__device__ float g_invS[KD];
__device__ float g_invN[KD];

__global__ void zero_kernel(float* out) {
    int i = blockIdx.x * blockDim.x + threadIdx.x;
    if (i < BD * KD) out[i] = 0.0f;                  // temp_exp_m_batch
    if (i < KD) {
        out[OFF_GSR + i] = 0.0f;                     // gamma_sr_sum
        g_colS[i] = 0.0f; g_colES[i] = 0.0f; g_colEN[i] = 0.0f;
    }
    if (i == 0) out[OFF_QZ] = 0.0f;                  // exp_q_z
}

// Column sums over V for seeds / exp_s / exp_n.
// stride is a multiple of 64, so each thread's k = tid & 63 is fixed.
__global__ void colsum_kernel(const float* __restrict__ seeds,
                              const float* __restrict__ exp_s,
                              const float* __restrict__ exp_n) {
    int tid = blockIdx.x * blockDim.x + threadIdx.x;
    int stride = gridDim.x * blockDim.x;
    float a = 0.0f, b = 0.0f, c = 0.0f;
    for (int i = tid; i < VD * KD; i += stride) {
        a += seeds[i];
        b += exp_s[i];
        c += exp_n[i];
    }
    int k = tid & (KD - 1);
    atomicAdd(&g_colS[k], a);
    atomicAdd(&g_colES[k], b);
    atomicAdd(&g_colEN[k], c);
}

__global__ void finalize_kernel() {
    int k = threadIdx.x;
    g_invS[k] = 1.0f / (MU_F * g_colS[k] + g_colES[k]);
    g_invN[k] = 1.0f / (BETA_F * (float)VD + g_colEN[k]);
}

__global__ __launch_bounds__(256) void main_kernel(
    const float* __restrict__ BOW,    // [B, V]
    const float* __restrict__ seeds,  // [V, K]
    const float* __restrict__ exp_m,  // [B, K]
    const float* __restrict__ exp_s,  // [V, K]
    const float* __restrict__ exp_n,  // [V, K]
    const float* __restrict__ pi,     // [K]
    float* __restrict__ out)
{
    __shared__ float sh_theta[BD * KD];   // exp_m + ETA
    __shared__ float sh_accM[BD * KD];    // temp_exp_m_batch partial
    __shared__ float sh_gsr[KD];
    __shared__ float sh_qz;

    for (int i = threadIdx.x; i < BD * KD; i += blockDim.x) {
        sh_theta[i] = exp_m[i] + ETA_F;
        sh_accM[i]  = 0.0f;
    }
    if (threadIdx.x < KD) sh_gsr[threadIdx.x] = 0.0f;
    if (threadIdx.x == 0) sh_qz = 0.0f;
    __syncthreads();

    const int lane  = threadIdx.x & 31;
    const int warp  = threadIdx.x >> 5;
    const int gwarp = blockIdx.x * (blockDim.x >> 5) + warp;
    const int nwarp = gridDim.x * (blockDim.x >> 5);
    const int k0 = lane, k1 = lane + 32;

    const float invS0 = g_invS[k0], invS1 = g_invS[k1];
    const float invN0 = g_invN[k0], invN1 = g_invN[k1];
    const float pi0 = pi[k0], pi1 = pi[k1];
    const float q0 = 1.0f - pi0, q1 = 1.0f - pi1;

    float accGsr0 = 0.0f, accGsr1 = 0.0f, accQz = 0.0f;

    for (int v = gwarp; v < VD; v += nwarp) {
        const int base = v * KD;
        const float sd0 = seeds[base + k0], sd1 = seeds[base + k1];
        const float ps0 = (MU_F  + exp_s[base + k0]) * invS0;
        const float ps1 = (MU_F  + exp_s[base + k1]) * invS1;
        const float pn0 = (BETA_F + exp_n[base + k0]) * invN0;
        const float pn1 = (BETA_F + exp_n[base + k1]) * invN1;
        const bool anyseed = __any_sync(0xffffffffu, (sd0 > 0.0f) || (sd1 > 0.0f));

        const float crr0 = (1.0f - sd0) * pn0, crr1 = (1.0f - sd1) * pn1;

        // stage counts for all 64 b: lane holds b=lane and b=lane+32
        const float cntA = BOW[lane * VD + v];
        const float cntB = BOW[(lane + 32) * VD + v];

        float aN0 = 0.0f, aN1 = 0.0f, aS0 = 0.0f, aS1 = 0.0f;

        if (!anyseed) {
            // FAST PATH (93.6% of rows): g_ss = g_sr = 0, gamma = g_rr normalized
            for (int b = 0; b < BD; b++) {
                const float cnt = __shfl_sync(0xffffffffu, (b < 32) ? cntA : cntB, b & 31);
                if (cnt <= 0.0f) continue;   // mask==0: contributes nothing
                float grr0 = sh_theta[b * KD + k0] * crr0;
                float grr1 = sh_theta[b * KD + k1] * crr1;
                float rp = grr0 + grr1;
                #pragma unroll
                for (int o = 16; o; o >>= 1)
                    rp += __shfl_xor_sync(0xffffffffu, rp, o);
                const float invr = __fdividef(1.0f, rp + MINI_F);
                grr0 *= invr; grr1 *= invr;
                aN0 += grr0 * cnt; aN1 += grr1 * cnt;
                accQz += grr0 * __logf(grr0 + MINI_F) + grr1 * __logf(grr1 + MINI_F);
                atomicAdd(&sh_accM[b * KD + k0], grr0 * cnt);
                atomicAdd(&sh_accM[b * KD + k1], grr1 * cnt);
            }
        } else {
            const float css0 = sd0 * ps0 * pi0, css1 = sd1 * ps1 * pi1;
            const float csr0 = sd0 * pn0 * q0,  csr1 = sd1 * pn1 * q1;
            for (int b = 0; b < BD; b++) {
                const float cnt = __shfl_sync(0xffffffffu, (b < 32) ? cntA : cntB, b & 31);
                if (cnt <= 0.0f) continue;
                const float th0 = sh_theta[b * KD + k0];
                const float th1 = sh_theta[b * KD + k1];
                float gss0 = th0 * css0, gss1 = th1 * css1;
                float gsr0 = th0 * csr0, gsr1 = th1 * csr1;
                float grr0 = th0 * crr0, grr1 = th1 * crr1;
                float sp = gss0 + gsr0 + gss1 + gsr1;
                float rp = grr0 + grr1;
                #pragma unroll
                for (int o = 16; o; o >>= 1) {
                    sp += __shfl_xor_sync(0xffffffffu, sp, o);
                    rp += __shfl_xor_sync(0xffffffffu, rp, o);
                }
                const float invs = __fdividef(1.0f, sp + MINI_F);
                const float invr = __fdividef(1.0f, rp + MINI_F);
                gss0 *= invs; gss1 *= invs;
                gsr0 *= invs; gsr1 *= invs;
                grr0 *= invr; grr1 *= invr;
                const float gam0 = pi0 * gss0 + q0 * (gsr0 + grr0);
                const float gam1 = pi1 * gss1 + q1 * (gsr1 + grr1);
                aN0 += (gsr0 + grr0) * cnt; aN1 += (gsr1 + grr1) * cnt;
                aS0 += gss0 * cnt;          aS1 += gss1 * cnt;
                accGsr0 += gsr0;            accGsr1 += gsr1;
                accQz += gam0 * __logf(gam0 + MINI_F) + gam1 * __logf(gam1 + MINI_F);
                atomicAdd(&sh_accM[b * KD + k0], gam0 * cnt);
                atomicAdd(&sh_accM[b * KD + k1], gam1 * cnt);
            }
        }
        out[OFF_N + base + k0] = aN0; out[OFF_N + base + k1] = aN1;
        out[OFF_S + base + k0] = aS0; out[OFF_S + base + k1] = aS1;
    }

    // gamma_sr_sum: register -> shared -> global
    atomicAdd(&sh_gsr[k0], accGsr0);
    atomicAdd(&sh_gsr[k1], accGsr1);
    // exp_q_z: warp butterfly -> shared -> global
    #pragma unroll
    for (int o = 16; o; o >>= 1)
        accQz += __shfl_xor_sync(0xffffffffu, accQz, o);
    if (lane == 0) atomicAdd(&sh_qz, accQz);
    __syncthreads();

    for (int i = threadIdx.x; i < BD * KD; i += blockDim.x) {
        const float x = sh_accM[i];
        if (x != 0.0f) atomicAdd(&out[i], x);
    }
    if (threadIdx.x < KD) atomicAdd(&out[OFF_GSR + threadIdx.x], sh_gsr[threadIdx.x]);
    if (threadIdx.x == 0) atomicAdd(&out[OFF_QZ], sh_qz);
}

extern "C" void kernel_launch(void* const* d_in, const int* in_sizes, int n_in,
                              void* d_out, int out_size) {
    const float* BOW   = (const float*)d_in[0];
    const float* seeds = (const float*)d_in[1];
    const float* exp_m = (const float*)d_in[2];
    const float* exp_s = (const float*)d_in[3];
    const float* exp_n = (const float*)d_in[4];
    const float* pi    = (const float*)d_in[5];
    float* out = (float*)d_out;

    zero_kernel<<<16, 256>>>(out);
    colsum_kernel<<<64, 256>>>(seeds, exp_s, exp_n);
    finalize_kernel<<<1, 64>>>();
    main_kernel<<<296, 256>>>(BOW, seeds, exp_m, exp_s, exp_n, pi, out);
}

// round 3
// speedup vs baseline: 1.3251x; 1.3251x over previous
#include <cuda_runtime.h>

// MixEHR_Seed: B=64, V=10000, K=64
// Inputs: batch_BOW [B,V], seeds [V,K], exp_m [B,K], exp_s [V,K], exp_n [V,K], pi [K]
// Output (fp32 concat): temp_exp_m_batch [B,K]=4096, temp_exp_n [V,K]=640000,
//                       temp_exp_s [V,K]=640000, gamma_sr_sum [K]=64, exp_q_z [1]

#define KD    64
#define BD    64
#define VD    10000
#define ETA_F  0.1f
#define BETA_F 0.05f
#define MU_F   0.05f
#define MINI_F 1e-6f

#define OFF_N   4096
#define OFF_S   644096
#define OFF_GSR 1284096
#define OFF_QZ  1284160

#define NBLK  740   // 5 CTAs x 148 SMs

__device__ float g_colS[KD];
__device__ float g_colES[KD];
__device__ float g_colEN[KD];
__device__ float g_scratch[NBLK * BD * KD];   // per-block exp_m partials (12.1 MB static)

__global__ void zero_kernel(float* out) {
    int i = blockIdx.x * blockDim.x + threadIdx.x;
    if (i < BD * KD) out[i] = 0.0f;                  // temp_exp_m_batch (reduce adds)
    if (i < KD) {
        out[OFF_GSR + i] = 0.0f;                     // gamma_sr_sum
        g_colS[i] = 0.0f; g_colES[i] = 0.0f; g_colEN[i] = 0.0f;
    }
    if (i == 0) out[OFF_QZ] = 0.0f;                  // exp_q_z
}

// Column sums over V for seeds / exp_s / exp_n. stride multiple of 64 -> fixed k per thread.
__global__ void colsum_kernel(const float* __restrict__ seeds,
                              const float* __restrict__ exp_s,
                              const float* __restrict__ exp_n) {
    int tid = blockIdx.x * blockDim.x + threadIdx.x;
    int stride = gridDim.x * blockDim.x;
    float a = 0.0f, b = 0.0f, c = 0.0f;
    for (int i = tid; i < VD * KD; i += stride) {
        a += seeds[i];
        b += exp_s[i];
        c += exp_n[i];
    }
    int k = tid & (KD - 1);
    atomicAdd(&g_colS[k], a);
    atomicAdd(&g_colES[k], b);
    atomicAdd(&g_colEN[k], c);
}

__global__ __launch_bounds__(256, 5) void main_kernel(
    const float* __restrict__ BOW,    // [B, V]
    const float* __restrict__ seeds,  // [V, K]
    const float* __restrict__ exp_m,  // [B, K]
    const float* __restrict__ exp_s,  // [V, K]
    const float* __restrict__ exp_n,  // [V, K]
    const float* __restrict__ pi,     // [K]
    float* __restrict__ out)
{
    __shared__ float sh_theta[BD * KD];   // exp_m + ETA
    __shared__ float sh_accM[BD * KD];    // temp_exp_m_batch partial
    __shared__ float sh_gsr[KD];
    __shared__ float sh_qz;

    for (int i = threadIdx.x; i < BD * KD; i += blockDim.x) {
        sh_theta[i] = exp_m[i] + ETA_F;
        sh_accM[i]  = 0.0f;
    }
    if (threadIdx.x < KD) sh_gsr[threadIdx.x] = 0.0f;
    if (threadIdx.x == 0) sh_qz = 0.0f;
    __syncthreads();

    const int lane  = threadIdx.x & 31;
    const int warp  = threadIdx.x >> 5;
    const int gwarp = blockIdx.x * (blockDim.x >> 5) + warp;
    const int nwarp = gridDim.x * (blockDim.x >> 5);
    const int k0 = lane, k1 = lane + 32;

    // column normalizers (finalize folded in: 2 rcp per thread)
    const float invS0 = 1.0f / (MU_F * g_colS[k0] + g_colES[k0]);
    const float invS1 = 1.0f / (MU_F * g_colS[k1] + g_colES[k1]);
    const float invN0 = 1.0f / (BETA_F * (float)VD + g_colEN[k0]);
    const float invN1 = 1.0f / (BETA_F * (float)VD + g_colEN[k1]);
    const float pi0 = pi[k0], pi1 = pi[k1];
    const float q0 = 1.0f - pi0, q1 = 1.0f - pi1;

    float accGsr0 = 0.0f, accGsr1 = 0.0f, accQz = 0.0f;

    for (int v = gwarp; v < VD; v += nwarp) {
        const int base = v * KD;
        const float sd0 = seeds[base + k0], sd1 = seeds[base + k1];
        const float ps0 = (MU_F  + exp_s[base + k0]) * invS0;
        const float ps1 = (MU_F  + exp_s[base + k1]) * invS1;
        const float pn0 = (BETA_F + exp_n[base + k0]) * invN0;
        const float pn1 = (BETA_F + exp_n[base + k1]) * invN1;
        const bool anyseed = __any_sync(0xffffffffu, (sd0 > 0.0f) || (sd1 > 0.0f));

        const float crr0 = (1.0f - sd0) * pn0, crr1 = (1.0f - sd1) * pn1;

        // counts for all 64 b: lane holds b=lane and b=lane+32
        const float cntA = BOW[lane * VD + v];
        const float cntB = BOW[(lane + 32) * VD + v];

        float aN0 = 0.0f, aN1 = 0.0f, aS0 = 0.0f, aS1 = 0.0f;

        if (!anyseed) {
            // FAST PATH (93.6% of rows): g_ss = g_sr = 0, gamma = normalized g_rr
            for (int b = 0; b < BD; b++) {
                const float cnt = __shfl_sync(0xffffffffu, (b < 32) ? cntA : cntB, b & 31);
                if (cnt <= 0.0f) continue;
                float grr0 = sh_theta[b * KD + k0] * crr0;
                float grr1 = sh_theta[b * KD + k1] * crr1;
                float rp = grr0 + grr1;
                #pragma unroll
                for (int o = 16; o; o >>= 1)
                    rp += __shfl_xor_sync(0xffffffffu, rp, o);
                const float invr = __fdividef(1.0f, rp + MINI_F);
                grr0 *= invr; grr1 *= invr;
                aN0 += grr0 * cnt; aN1 += grr1 * cnt;
                accQz += grr0 * __logf(grr0 + MINI_F) + grr1 * __logf(grr1 + MINI_F);
                atomicAdd(&sh_accM[b * KD + k0], grr0 * cnt);
                atomicAdd(&sh_accM[b * KD + k1], grr1 * cnt);
            }
        } else {
            const float css0 = sd0 * ps0 * pi0, css1 = sd1 * ps1 * pi1;
            const float csr0 = sd0 * pn0 * q0,  csr1 = sd1 * pn1 * q1;
            for (int b = 0; b < BD; b++) {
                const float cnt = __shfl_sync(0xffffffffu, (b < 32) ? cntA : cntB, b & 31);
                if (cnt <= 0.0f) continue;
                const float th0 = sh_theta[b * KD + k0];
                const float th1 = sh_theta[b * KD + k1];
                float gss0 = th0 * css0, gss1 = th1 * css1;
                float gsr0 = th0 * csr0, gsr1 = th1 * csr1;
                float grr0 = th0 * crr0, grr1 = th1 * crr1;
                float sp = gss0 + gsr0 + gss1 + gsr1;
                float rp = grr0 + grr1;
                #pragma unroll
                for (int o = 16; o; o >>= 1) {
                    sp += __shfl_xor_sync(0xffffffffu, sp, o);
                    rp += __shfl_xor_sync(0xffffffffu, rp, o);
                }
                const float invs = __fdividef(1.0f, sp + MINI_F);
                const float invr = __fdividef(1.0f, rp + MINI_F);
                gss0 *= invs; gss1 *= invs;
                gsr0 *= invs; gsr1 *= invs;
                grr0 *= invr; grr1 *= invr;
                const float gam0 = pi0 * gss0 + q0 * (gsr0 + grr0);
                const float gam1 = pi1 * gss1 + q1 * (gsr1 + grr1);
                aN0 += (gsr0 + grr0) * cnt; aN1 += (gsr1 + grr1) * cnt;
                aS0 += gss0 * cnt;          aS1 += gss1 * cnt;
                accGsr0 += gsr0;            accGsr1 += gsr1;
                accQz += gam0 * __logf(gam0 + MINI_F) + gam1 * __logf(gam1 + MINI_F);
                atomicAdd(&sh_accM[b * KD + k0], gam0 * cnt);
                atomicAdd(&sh_accM[b * KD + k1], gam1 * cnt);
            }
        }
        out[OFF_N + base + k0] = aN0; out[OFF_N + base + k1] = aN1;
        out[OFF_S + base + k0] = aS0; out[OFF_S + base + k1] = aS1;
    }

    // gamma_sr_sum: register -> shared -> global
    atomicAdd(&sh_gsr[k0], accGsr0);
    atomicAdd(&sh_gsr[k1], accGsr1);
    // exp_q_z: warp butterfly -> shared -> global
    #pragma unroll
    for (int o = 16; o; o >>= 1)
        accQz += __shfl_xor_sync(0xffffffffu, accQz, o);
    if (lane == 0) atomicAdd(&sh_qz, accQz);
    __syncthreads();

    // exp_m partials -> private scratch slice (no contended global atomics)
    {
        float* dst = &g_scratch[blockIdx.x * (BD * KD)];
        for (int i = threadIdx.x; i < BD * KD; i += blockDim.x)
            dst[i] = sh_accM[i];
    }
    if (threadIdx.x < KD) atomicAdd(&out[OFF_GSR + threadIdx.x], sh_gsr[threadIdx.x]);
    if (threadIdx.x == 0) atomicAdd(&out[OFF_QZ], sh_qz);
}

// Sum scratch[NBLK][4096] -> out[0..4095]. grid=(16,4): y-chunks of 185 blocks.
__global__ void reduce_m_kernel(float* __restrict__ out) {
    const int i = blockIdx.x * blockDim.x + threadIdx.x;   // 0..4095
    const int j0 = blockIdx.y * 185;
    const int j1 = j0 + 185;
    float s0 = 0.0f, s1 = 0.0f, s2 = 0.0f, s3 = 0.0f;
    int j = j0;
    for (; j + 4 <= j1; j += 4) {
        s0 += g_scratch[(j + 0) * (BD * KD) + i];
        s1 += g_scratch[(j + 1) * (BD * KD) + i];
        s2 += g_scratch[(j + 2) * (BD * KD) + i];
        s3 += g_scratch[(j + 3) * (BD * KD) + i];
    }
    for (; j < j1; j++) s0 += g_scratch[j * (BD * KD) + i];
    atomicAdd(&out[i], (s0 + s1) + (s2 + s3));
}

extern "C" void kernel_launch(void* const* d_in, const int* in_sizes, int n_in,
                              void* d_out, int out_size) {
    const float* BOW   = (const float*)d_in[0];
    const float* seeds = (const float*)d_in[1];
    const float* exp_m = (const float*)d_in[2];
    const float* exp_s = (const float*)d_in[3];
    const float* exp_n = (const float*)d_in[4];
    const float* pi    = (const float*)d_in[5];
    float* out = (float*)d_out;

    zero_kernel<<<16, 256>>>(out);
    colsum_kernel<<<64, 256>>>(seeds, exp_s, exp_n);
    main_kernel<<<NBLK, 256>>>(BOW, seeds, exp_m, exp_s, exp_n, pi, out);
    reduce_m_kernel<<<dim3(16, 4), 256>>>(out);
}

// round 5
// speedup vs baseline: 1.6482x; 1.2439x over previous
#include <cuda_runtime.h>

// MixEHR_Seed: B=64, V=10000, K=64
// out: temp_exp_m_batch [64,64], temp_exp_n [V,K], temp_exp_s [V,K], gamma_sr_sum [K], exp_q_z [1]

#define KD    64
#define BD    64
#define VD    10000
#define TQ    4                 // v per tile
#define NTILE (VD / TQ)         // 2500
#define NBLK  444               // 3 CTAs x 148 SMs
#define ETA_F  0.1f
#define BETA_F 0.05f
#define MU_F   0.05f
#define MINI_F 1e-6f

#define OFF_N   4096
#define OFF_S   644096
#define OFF_GSR 1284096
#define OFF_QZ  1284160

__device__ float g_colS[KD];
__device__ float g_colES[KD];
__device__ float g_colEN[KD];
__device__ float g_scratch[NBLK * BD * KD];   // per-block exp_m partials

__device__ __forceinline__ float warp_sum(float x) {
    #pragma unroll
    for (int o = 16; o; o >>= 1)
        x += __shfl_xor_sync(0xffffffffu, x, o);
    return x;
}

__global__ void zero_kernel(float* out) {
    int i = blockIdx.x * blockDim.x + threadIdx.x;
    if (i < BD * KD) out[i] = 0.0f;
    if (i < KD) {
        out[OFF_GSR + i] = 0.0f;
        g_colS[i] = 0.0f; g_colES[i] = 0.0f; g_colEN[i] = 0.0f;
    }
    if (i == 0) out[OFF_QZ] = 0.0f;
}

__global__ void colsum_kernel(const float* __restrict__ seeds,
                              const float* __restrict__ exp_s,
                              const float* __restrict__ exp_n) {
    int tid = blockIdx.x * blockDim.x + threadIdx.x;
    int stride = gridDim.x * blockDim.x;
    float a = 0.0f, b = 0.0f, c = 0.0f;
    for (int i = tid; i < VD * KD; i += stride) {
        a += seeds[i]; b += exp_s[i]; c += exp_n[i];
    }
    int k = tid & (KD - 1);
    atomicAdd(&g_colS[k], a);
    atomicAdd(&g_colES[k], b);
    atomicAdd(&g_colEN[k], c);
}

__global__ __launch_bounds__(256, 3) void main_kernel(
    const float* __restrict__ BOW,
    const float* __restrict__ seeds,
    const float* __restrict__ exp_m,
    const float* __restrict__ exp_s,
    const float* __restrict__ exp_n,
    const float* __restrict__ pi,
    float* __restrict__ out)
{
    __shared__ float2 sh_thlt[BD * KD];     // {theta, log(theta)}  32 KB
    __shared__ float  sh_pN[8][TQ * KD];    // aN partials per warp  8 KB
    __shared__ float  sh_pS[8][TQ * KD];    // aS partials per warp  8 KB
    __shared__ float  sh_gsr[KD];
    __shared__ float  sh_qz;

    for (int i = threadIdx.x; i < BD * KD; i += blockDim.x) {
        float th = exp_m[i] + ETA_F;
        sh_thlt[i] = make_float2(th, __logf(th));
    }
    if (threadIdx.x < KD) sh_gsr[threadIdx.x] = 0.0f;
    if (threadIdx.x == 0) sh_qz = 0.0f;
    __syncthreads();

    const int lane = threadIdx.x & 31;
    const int warp = threadIdx.x >> 5;
    const int k0 = lane, k1 = lane + 32;
    const int b0 = warp * 8;                // this warp owns b in [b0, b0+8)

    const float invS0 = 1.0f / (MU_F * g_colS[k0] + g_colES[k0]);
    const float invS1 = 1.0f / (MU_F * g_colS[k1] + g_colES[k1]);
    const float invN0 = 1.0f / (BETA_F * (float)VD + g_colEN[k0]);
    const float invN1 = 1.0f / (BETA_F * (float)VD + g_colEN[k1]);
    const float pi0 = pi[k0], pi1 = pi[k1];
    const float q0 = 1.0f - pi0, q1 = 1.0f - pi1;

    float accM0[8], accM1[8];
    #pragma unroll
    for (int j = 0; j < 8; j++) { accM0[j] = 0.0f; accM1[j] = 0.0f; }
    float accGsr0 = 0.0f, accGsr1 = 0.0f, accQz = 0.0f;

    for (int tile = blockIdx.x; tile < NTILE; tile += gridDim.x) {
        const int v0 = tile * TQ;

        // per-row constants
        float crr0[TQ], crr1[TQ], lc0[TQ], lc1[TQ];
        bool rowseed[TQ];
        bool tileseed = false;
        #pragma unroll
        for (int t = 0; t < TQ; t++) {
            const int base = (v0 + t) * KD;
            const float sd0 = seeds[base + k0], sd1 = seeds[base + k1];
            const float pn0 = (BETA_F + exp_n[base + k0]) * invN0;
            const float pn1 = (BETA_F + exp_n[base + k1]) * invN1;
            crr0[t] = (1.0f - sd0) * pn0;
            crr1[t] = (1.0f - sd1) * pn1;
            rowseed[t] = __ballot_sync(0xffffffffu, (sd0 > 0.0f) || (sd1 > 0.0f)) != 0u;
            tileseed |= rowseed[t];
            lc0[t] = __logf(crr0[t] + 1e-30f);
            lc1[t] = __logf(crr1[t] + 1e-30f);
        }

        float aN0[TQ], aN1[TQ], aS0[TQ], aS1[TQ];
        #pragma unroll
        for (int t = 0; t < TQ; t++) { aN0[t]=0.f; aN1[t]=0.f; aS0[t]=0.f; aS1[t]=0.f; }

        if (!tileseed) {
            // ---------------- FAST PATH ----------------
            #pragma unroll
            for (int j = 0; j < 8; j++) {
                const int b = b0 + j;
                const float4 c4 = *reinterpret_cast<const float4*>(BOW + b * VD + v0);
                const float cntv[TQ] = {c4.x, c4.y, c4.z, c4.w};
                const float2 tl0 = sh_thlt[b * KD + k0];
                const float2 tl1 = sh_thlt[b * KD + k1];

                float grr0v[TQ], grr1v[TQ], rpv[TQ];
                #pragma unroll
                for (int t = 0; t < TQ; t++) {
                    grr0v[t] = tl0.x * crr0[t];
                    grr1v[t] = tl1.x * crr1[t];
                    rpv[t] = grr0v[t] + grr1v[t];
                }
                // 4 independent butterflies (ILP covers SHFL latency)
                #pragma unroll
                for (int o = 16; o; o >>= 1) {
                    #pragma unroll
                    for (int t = 0; t < TQ; t++)
                        rpv[t] += __shfl_xor_sync(0xffffffffu, rpv[t], o);
                }
                #pragma unroll
                for (int t = 0; t < TQ; t++) {
                    const float rpm = rpv[t] + MINI_F;
                    const float inv = __fdividef(1.0f, rpm);
                    const float lrp = __logf(rpm);
                    const float g0 = grr0v[t] * inv;
                    const float g1 = grr1v[t] * inv;
                    const float cnt = cntv[t];
                    const float p0 = g0 * cnt, p1 = g1 * cnt;
                    aN0[t] += p0; aN1[t] += p1;
                    accM0[j] += p0; accM1[j] += p1;
                    const float m = (cnt > 0.0f) ? 1.0f : 0.0f;
                    const float e = g0 * ((tl0.y + lc0[t]) - lrp)
                                  + g1 * ((tl1.y + lc1[t]) - lrp);
                    accQz = fmaf(m, e, accQz);
                }
            }
        } else {
            // ---------------- SEED-TILE PATH ----------------
            #pragma unroll
            for (int j = 0; j < 8; j++) {
                const int b = b0 + j;
                const float4 c4 = *reinterpret_cast<const float4*>(BOW + b * VD + v0);
                const float cntv[TQ] = {c4.x, c4.y, c4.z, c4.w};
                const float2 tl0 = sh_thlt[b * KD + k0];
                const float2 tl1 = sh_thlt[b * KD + k1];

                #pragma unroll
                for (int t = 0; t < TQ; t++) {
                    const float cnt = cntv[t];
                    const float m = (cnt > 0.0f) ? 1.0f : 0.0f;
                    if (rowseed[t]) {
                        const int base = (v0 + t) * KD;
                        const float sd0 = seeds[base + k0], sd1 = seeds[base + k1];
                        const float ps0 = (MU_F  + exp_s[base + k0]) * invS0;
                        const float ps1 = (MU_F  + exp_s[base + k1]) * invS1;
                        const float pn0 = (BETA_F + exp_n[base + k0]) * invN0;
                        const float pn1 = (BETA_F + exp_n[base + k1]) * invN1;
                        float gss0 = tl0.x * sd0 * ps0 * pi0;
                        float gss1 = tl1.x * sd1 * ps1 * pi1;
                        float gsr0 = tl0.x * sd0 * pn0 * q0;
                        float gsr1 = tl1.x * sd1 * pn1 * q1;
                        float grr0 = tl0.x * crr0[t];
                        float grr1 = tl1.x * crr1[t];
                        float sp = gss0 + gsr0 + gss1 + gsr1;
                        float rp = grr0 + grr1;
                        #pragma unroll
                        for (int o = 16; o; o >>= 1) {
                            sp += __shfl_xor_sync(0xffffffffu, sp, o);
                            rp += __shfl_xor_sync(0xffffffffu, rp, o);
                        }
                        const float invs = __fdividef(1.0f, sp + MINI_F);
                        const float invr = __fdividef(1.0f, rp + MINI_F);
                        gss0 *= invs; gss1 *= invs;
                        gsr0 *= invs; gsr1 *= invs;
                        grr0 *= invr; grr1 *= invr;
                        const float gam0 = pi0 * gss0 + q0 * (gsr0 + grr0);
                        const float gam1 = pi1 * gss1 + q1 * (gsr1 + grr1);
                        accM0[j] += gam0 * cnt; accM1[j] += gam1 * cnt;
                        aN0[t] += (gsr0 + grr0) * cnt; aN1[t] += (gsr1 + grr1) * cnt;
                        aS0[t] += gss0 * cnt;          aS1[t] += gss1 * cnt;
                        accGsr0 += m * gsr0;           accGsr1 += m * gsr1;
                        accQz += m * (gam0 * __logf(gam0 + MINI_F)
                                    + gam1 * __logf(gam1 + MINI_F));
                    } else {
                        float grr0 = tl0.x * crr0[t];
                        float grr1 = tl1.x * crr1[t];
                        const float rpm = warp_sum(grr0 + grr1) + MINI_F;
                        const float inv = __fdividef(1.0f, rpm);
                        const float lrp = __logf(rpm);
                        const float g0 = grr0 * inv, g1 = grr1 * inv;
                        const float p0 = g0 * cnt, p1 = g1 * cnt;
                        aN0[t] += p0; aN1[t] += p1;
                        accM0[j] += p0; accM1[j] += p1;
                        const float e = g0 * ((tl0.y + lc0[t]) - lrp)
                                      + g1 * ((tl1.y + lc1[t]) - lrp);
                        accQz = fmaf(m, e, accQz);
                    }
                }
            }
        }

        // write per-warp partials, cross-warp reduce, store temp_exp_n / temp_exp_s
        #pragma unroll
        for (int t = 0; t < TQ; t++) {
            sh_pN[warp][t * KD + k0] = aN0[t];
            sh_pN[warp][t * KD + k1] = aN1[t];
            sh_pS[warp][t * KD + k0] = aS0[t];
            sh_pS[warp][t * KD + k1] = aS1[t];
        }
        __syncthreads();
        {
            const int tid = threadIdx.x;   // tid = t*64 + k
            float sN = 0.0f;
            #pragma unroll
            for (int w = 0; w < 8; w++) sN += sh_pN[w][tid];
            out[OFF_N + v0 * KD + tid] = sN;
            float sS = 0.0f;
            if (tileseed) {
                #pragma unroll
                for (int w = 0; w < 8; w++) sS += sh_pS[w][tid];
            }
            out[OFF_S + v0 * KD + tid] = sS;
        }
        __syncthreads();
    }

    // epilogue: exp_m register partials -> private scratch (no atomics)
    {
        float* dst = g_scratch + blockIdx.x * (BD * KD);
        #pragma unroll
        for (int j = 0; j < 8; j++) {
            dst[(b0 + j) * KD + k0] = accM0[j];
            dst[(b0 + j) * KD + k1] = accM1[j];
        }
    }
    atomicAdd(&sh_gsr[k0], accGsr0);
    atomicAdd(&sh_gsr[k1], accGsr1);
    const float qzw = warp_sum(accQz);
    if (lane == 0) atomicAdd(&sh_qz, qzw);
    __syncthreads();
    if (threadIdx.x < KD) atomicAdd(&out[OFF_GSR + threadIdx.x], sh_gsr[threadIdx.x]);
    if (threadIdx.x == 0) atomicAdd(&out[OFF_QZ], sh_qz);
}

// Sum scratch[NBLK][4096] -> out[0..4095]. grid (16, 37): 12 slices per y-chunk.
__global__ void reduce_m_kernel(float* __restrict__ out) {
    const int i = blockIdx.x * blockDim.x + threadIdx.x;   // 0..4095
    const int j0 = blockIdx.y * 12;
    float s = 0.0f;
    #pragma unroll
    for (int j = 0; j < 12; j++)
        s += g_scratch[(j0 + j) * (BD * KD) + i];
    atomicAdd(&out[i], s);
}

extern "C" void kernel_launch(void* const* d_in, const int* in_sizes, int n_in,
                              void* d_out, int out_size) {
    const float* BOW   = (const float*)d_in[0];
    const float* seeds = (const float*)d_in[1];
    const float* exp_m = (const float*)d_in[2];
    const float* exp_s = (const float*)d_in[3];
    const float* exp_n = (const float*)d_in[4];
    const float* pi    = (const float*)d_in[5];
    float* out = (float*)d_out;

    zero_kernel<<<16, 256>>>(out);
    colsum_kernel<<<148, 256>>>(seeds, exp_s, exp_n);
    main_kernel<<<NBLK, 256>>>(BOW, seeds, exp_m, exp_s, exp_n, pi, out);
    reduce_m_kernel<<<dim3(16, 37), 256>>>(out);
}